// round 6
// baseline (speedup 1.0000x reference)
#include <cuda_runtime.h>
#include <cstdint>

#define NN     8
#define CC     21
#define HWP    262144      // 512*512
#define NQUAD  (HWP / 4)
#define OLDCL  16
#define IGN    255
#define NCLS   6
#define GX     74          // 74*8 = 592 blocks
#define TPB    256

__device__ float        g_part[NN * 16];
__device__ unsigned int g_done = 0;

// ---- packed f32x2 helpers (sm_103a) ----
__device__ __forceinline__ unsigned long long mul2(unsigned long long a, unsigned long long b) {
    unsigned long long d; asm("mul.rn.f32x2 %0,%1,%2;" : "=l"(d) : "l"(a), "l"(b)); return d;
}
__device__ __forceinline__ unsigned long long add2(unsigned long long a, unsigned long long b) {
    unsigned long long d; asm("add.rn.f32x2 %0,%1,%2;" : "=l"(d) : "l"(a), "l"(b)); return d;
}
__device__ __forceinline__ unsigned long long fma2(unsigned long long a, unsigned long long b, unsigned long long c) {
    unsigned long long d; asm("fma.rn.f32x2 %0,%1,%2,%3;" : "=l"(d) : "l"(a), "l"(b), "l"(c)); return d;
}
__device__ __forceinline__ unsigned long long pack2(float a, float b) {
    unsigned long long d; asm("mov.b64 %0,{%1,%2};" : "=l"(d) : "f"(a), "f"(b)); return d;
}
__device__ __forceinline__ float2 unpack2(unsigned long long v) {
    float2 r; asm("mov.b64 {%0,%1},%2;" : "=f"(r.x), "=f"(r.y) : "l"(v)); return r;
}
__device__ __forceinline__ float ex2f(float x) { float y; asm("ex2.approx.f32 %0,%1;" : "=f"(y) : "f"(x)); return y; }
__device__ __forceinline__ float lg2f(float x) { float y; asm("lg2.approx.f32 %0,%1;" : "=f"(y) : "f"(x)); return y; }

// packed exp(x) for 2 lanes via FFMA poly: e^x = 2^(x*log2e), magic-number
// range reduction, degree-4 Taylor of 2^f on f in [-0.5, 0.5] (rel err ~4e-5).
__device__ __forceinline__ unsigned long long exp2pair(unsigned long long x,
    unsigned long long LOG2E2, unsigned long long MAGIC2, unsigned long long NMAGIC2,
    unsigned long long NONE2, unsigned long long C4, unsigned long long C3,
    unsigned long long C2, unsigned long long C1, unsigned long long ONE2) {
    unsigned long long y = mul2(x, LOG2E2);
    unsigned long long t = add2(y, MAGIC2);      // y + 1.5*2^23  -> n in mantissa
    unsigned long long g = add2(t, NMAGIC2);     // = round(y)
    unsigned long long f = fma2(g, NONE2, y);    // f = y - n, in [-0.5, 0.5]
    unsigned long long p = fma2(f, C4, C3);
    p = fma2(f, p, C2);
    p = fma2(f, p, C1);
    p = fma2(f, p, ONE2);
    // scale = 2^n from t's integer bits: tbits = 0x4B400000 + n  ->
    // sbits = tbits * 2^23 + (127<<23)  (mod 2^32)  = (n+127)<<23
    uint32_t tlo, thi;
    asm("mov.b64 {%0,%1},%2;" : "=r"(tlo), "=r"(thi) : "l"(t));
    uint32_t slo = tlo * 8388608u + 0x3F800000u;
    uint32_t shi = thi * 8388608u + 0x3F800000u;
    unsigned long long sc;
    asm("mov.b64 %0,{%1,%2};" : "=l"(sc) : "r"(slo), "r"(shi));
    return mul2(p, sc);
}

__global__ __launch_bounds__(TPB) void fused_k(const float* __restrict__ in,
                                               const int* __restrict__ tg,
                                               float* __restrict__ out) {
    const float LN2 = 0.6931471805599453f;
    const unsigned long long LOG2E2 = pack2(1.4426950408889634f, 1.4426950408889634f);
    const unsigned long long MAGIC2 = pack2(12582912.0f, 12582912.0f);
    const unsigned long long NMAGIC2 = pack2(-12582912.0f, -12582912.0f);
    const unsigned long long NONE2 = pack2(-1.0f, -1.0f);
    const unsigned long long ONE2 = pack2(1.0f, 1.0f);
    const unsigned long long C1 = pack2(0.6931471805f, 0.6931471805f);
    const unsigned long long C2 = pack2(0.2402265069f, 0.2402265069f);
    const unsigned long long C3 = pack2(0.0555041087f, 0.0555041087f);
    const unsigned long long C4 = pack2(0.0096181291f, 0.0096181291f);

    int n = blockIdx.y;
    const float* base = in + (size_t)n * CC * HWP;
    const int*   t    = tg + (size_t)n * HWP;

    float accT[NCLS] = {0, 0, 0, 0, 0, 0};
    unsigned long long hcnt = 0ull;      // 7 x 9-bit class counters (slot 6 = invalid)

    const int stride = GX * TPB;
    for (int g = blockIdx.x * TPB + threadIdx.x; g < NQUAD; g += stride) {
        int p = g * 4;
        int4 tv = *reinterpret_cast<const int4*>(t + p);

        unsigned long long s_xy = 0ull, s_zw = 0ull;   // packed {0.f,0.f}

        // ---- channels 0..15 via MUFU EX2, packed pre-mul + packed accumulate ----
#pragma unroll
        for (int b = 0; b < 2; b++) {
            float4 xv[8];
#pragma unroll
            for (int j = 0; j < 8; j++)
                xv[j] = __ldcs(reinterpret_cast<const float4*>(
                    base + (size_t)(b * 8 + j) * HWP + p));
#pragma unroll
            for (int j = 0; j < 8; j++) {
                unsigned long long y0 = mul2(pack2(xv[j].x, xv[j].y), LOG2E2);
                unsigned long long y1 = mul2(pack2(xv[j].z, xv[j].w), LOG2E2);
                float2 a = unpack2(y0), b2 = unpack2(y1);
                s_xy = add2(s_xy, pack2(ex2f(a.x), ex2f(a.y)));
                s_zw = add2(s_zw, pack2(ex2f(b2.x), ex2f(b2.y)));
            }
        }
        unsigned long long s16_xy = s_xy, s16_zw = s_zw;

        // ---- channels 16..20 via packed FFMA exp (no MUFU), plus label-select ----
        float4 xv5[5];
#pragma unroll
        for (int j = 0; j < 5; j++)
            xv5[j] = __ldcs(reinterpret_cast<const float4*>(
                base + (size_t)(OLDCL + j) * HWP + p));
        float4 sel = make_float4(0.f, 0.f, 0.f, 0.f);
#pragma unroll
        for (int j = 0; j < 5; j++) {
            int c = OLDCL + j;
            sel.x = (c == tv.x) ? xv5[j].x : sel.x;
            sel.y = (c == tv.y) ? xv5[j].y : sel.y;
            sel.z = (c == tv.z) ? xv5[j].z : sel.z;
            sel.w = (c == tv.w) ? xv5[j].w : sel.w;
            s_xy = add2(s_xy, exp2pair(pack2(xv5[j].x, xv5[j].y),
                        LOG2E2, MAGIC2, NMAGIC2, NONE2, C4, C3, C2, C1, ONE2));
            s_zw = add2(s_zw, exp2pair(pack2(xv5[j].z, xv5[j].w),
                        LOG2E2, MAGIC2, NMAGIC2, NONE2, C4, C3, C2, C1, ONE2));
        }

        // ---- per-pixel finalize ----
        float2 sA = unpack2(s_xy), sB = unpack2(s_zw);
        float2 qA = unpack2(s16_xy), qB = unpack2(s16_zw);
        float sv[4]  = {sA.x, sA.y, sB.x, sB.y};
        float qv[4]  = {qA.x, qA.y, qB.x, qB.y};
        float se[4]  = {sel.x, sel.y, sel.z, sel.w};
        int   tj[4]  = {tv.x, tv.y, tv.z, tv.w};
#pragma unroll
        for (int px = 0; px < 4; px++) {
            float L21  = lg2f(sv[px]) * LN2;
            float lg16 = lg2f(qv[px]) * LN2;
            int idx  = (tj[px] < OLDCL) ? 0 : (tj[px] - (OLDCL - 1)); // 0..5 valid, big if IGN
            int code = (idx > 6) ? 6 : idx;                           // slot 6 = invalid
            hcnt += 1ull << (9 * code);
            float lp = ((idx == 0) ? lg16 : se[px]) - L21;
#pragma unroll
            for (int k = 0; k < NCLS; k++)
                if (idx == k) accT[k] += lp;
        }
    }

    // ---- block reduction of 13 values (6 T + 6 H + vcount) ----
    float vals[13];
    float vcf = 0.0f;
#pragma unroll
    for (int k = 0; k < NCLS; k++) {
        vals[k] = accT[k];
        float c = (float)((hcnt >> (9 * k)) & 511ull);
        vals[k + NCLS] = c;
        vcf += c;
    }
    vals[12] = vcf;

    __shared__ float sh[8][13];
    int lane = threadIdx.x & 31;
    int wid  = threadIdx.x >> 5;
#pragma unroll
    for (int k = 0; k < 13; k++) {
        float v = vals[k];
        v += __shfl_down_sync(0xffffffffu, v, 16);
        v += __shfl_down_sync(0xffffffffu, v, 8);
        v += __shfl_down_sync(0xffffffffu, v, 4);
        v += __shfl_down_sync(0xffffffffu, v, 2);
        v += __shfl_down_sync(0xffffffffu, v, 1);
        if (lane == 0) sh[wid][k] = v;
    }
    __syncthreads();
    if (wid == 0) {
#pragma unroll
        for (int k = 0; k < 13; k++) {
            float v = (lane < 8) ? sh[lane][k] : 0.0f;
            v += __shfl_down_sync(0xffffffffu, v, 4);
            v += __shfl_down_sync(0xffffffffu, v, 2);
            v += __shfl_down_sync(0xffffffffu, v, 1);
            if (lane == 0) atomicAdd(&g_part[n * 16 + k], v);
        }
    }

    // ---- last-block finalize ----
    __shared__ int is_last;
    __threadfence();
    if (threadIdx.x == 0) {
        unsigned int v = atomicAdd(&g_done, 1u);
        is_last = (v == (unsigned)(GX * NN) - 1u) ? 1 : 0;
    }
    __syncthreads();
    if (!is_last) return;

    __threadfence();
    if (wid == 0) {
        float num = 0.0f, den = 0.0f;
        if (lane < NN) {
            float T[NCLS], H[NCLS];
#pragma unroll
            for (int k = 0; k < NCLS; k++) {
                T[k] = __ldcg(&g_part[lane * 16 + k]);
                H[k] = __ldcg(&g_part[lane * 16 + NCLS + k]);
            }
            float vcn = __ldcg(&g_part[lane * 16 + 12]);
            float hs[NCLS], S = 0.0f;
#pragma unroll
            for (int k = 0; k < NCLS; k++) {
                hs[k] = (H[k] == 0.0f) ? 1.0f : H[k];
                S += hs[k];
            }
            float c = 0.0f;
#pragma unroll
            for (int k = 0; k < NCLS; k++) c += (S / hs[k]) * T[k];
            num = c;
            den = vcn;
        }
        num += __shfl_down_sync(0xffffffffu, num, 4);
        den += __shfl_down_sync(0xffffffffu, den, 4);
        num += __shfl_down_sync(0xffffffffu, num, 2);
        den += __shfl_down_sync(0xffffffffu, den, 2);
        num += __shfl_down_sync(0xffffffffu, num, 1);
        den += __shfl_down_sync(0xffffffffu, den, 1);
        if (lane == 0) out[0] = -num / den;
    }
    __syncthreads();
    if (threadIdx.x < NN * 16) g_part[threadIdx.x] = 0.0f;
    if (threadIdx.x == 0)      g_done = 0;
}

extern "C" void kernel_launch(void* const* d_in, const int* in_sizes, int n_in,
                              void* d_out, int out_size) {
    const float* in;
    const int*   tg;
    if (in_sizes[0] > in_sizes[1]) {
        in = (const float*)d_in[0];
        tg = (const int*)d_in[1];
    } else {
        in = (const float*)d_in[1];
        tg = (const int*)d_in[0];
    }
    dim3 grid(GX, NN);
    fused_k<<<grid, TPB>>>(in, tg, (float*)d_out);
}

// round 7
// speedup vs baseline: 1.0073x; 1.0073x over previous
#include <cuda_runtime.h>
#include <cstdint>

#define NN     8
#define CC     21
#define HWP    262144      // 512*512
#define NQUAD  (HWP / 4)
#define OLDCL  16
#define IGN    255
#define NCLS   6
#define GX     74          // 74*8 = 592 blocks = one wave at 4 blocks/SM
#define TPB    256

__device__ float        g_part[NN * 16];
__device__ unsigned int g_done = 0;

__device__ __forceinline__ float lg2f(float x) {
    float y; asm("lg2.approx.f32 %0,%1;" : "=f"(y) : "f"(x)); return y;
}

__global__ __launch_bounds__(TPB) void fused_k(const float* __restrict__ in,
                                               const int* __restrict__ tg,
                                               float* __restrict__ out) {
    const float LN2 = 0.6931471805599453f;

    int n = blockIdx.y;
    const float* base = in + (size_t)n * CC * HWP;
    const int*   t    = tg + (size_t)n * HWP;

    float accT[NCLS] = {0, 0, 0, 0, 0, 0};
    unsigned long long hcnt = 0ull;      // 7 x 9-bit counters (slots 0..5 classes, 6 invalid)

    const int stride = GX * TPB;
    for (int g = blockIdx.x * TPB + threadIdx.x; g < NQUAD; g += stride) {
        int p = g * 4;
        int4 tv = *reinterpret_cast<const int4*>(t + p);

        float4 s = make_float4(0.f, 0.f, 0.f, 0.f);
        float4 s16;

        // ---- channels 0..15 in two batches of 8 (loads hoisted for MLP) ----
#pragma unroll
        for (int b = 0; b < 2; b++) {
            float4 xv[8];
#pragma unroll
            for (int j = 0; j < 8; j++)
                xv[j] = __ldcs(reinterpret_cast<const float4*>(
                    base + (size_t)(b * 8 + j) * HWP + p));
#pragma unroll
            for (int j = 0; j < 8; j++) {
                s.x += __expf(xv[j].x);
                s.y += __expf(xv[j].y);
                s.z += __expf(xv[j].z);
                s.w += __expf(xv[j].w);
            }
        }
        s16 = s;                                    // sum of exp over channels 0..15

        // ---- channels 16..20, batch of 5 ----
        {
            float4 xv[5];
#pragma unroll
            for (int j = 0; j < 5; j++)
                xv[j] = __ldcs(reinterpret_cast<const float4*>(
                    base + (size_t)(OLDCL + j) * HWP + p));
#pragma unroll
            for (int j = 0; j < 5; j++) {
                s.x += __expf(xv[j].x);
                s.y += __expf(xv[j].y);
                s.z += __expf(xv[j].z);
                s.w += __expf(xv[j].w);
            }
        }

        // ---- per-pixel finalize: gather x[label] instead of select-tracking ----
        int   tj[4] = {tv.x, tv.y, tv.z, tv.w};
        float sv[4] = {s.x, s.y, s.z, s.w};
        float qv[4] = {s16.x, s16.y, s16.z, s16.w};
#pragma unroll
        for (int px = 0; px < 4; px++) {
            int idx  = (tj[px] < OLDCL) ? 0 : (tj[px] - (OLDCL - 1)); // 0..5, big if IGN
            int code = (idx > 6) ? 6 : idx;                           // 6 = invalid slot
            hcnt += 1ull << (9 * code);
            // lines for channels 16..20 at this pixel were just streamed (L1/L2 hit)
            float se = 0.0f;
            if (tj[px] >= OLDCL) {
                int c = (tj[px] > CC - 1) ? (CC - 1) : tj[px];        // clamp (IGN safe)
                se = __ldg(base + (size_t)c * HWP + p + px);
            }
            float a  = lg2f(sv[px]);
            float lp = (idx == 0) ? ((lg2f(qv[px]) - a) * LN2)
                                  : fmaf(-LN2, a, se);
#pragma unroll
            for (int k = 0; k < NCLS; k++)
                if (idx == k) accT[k] += lp;
        }
    }

    // ---- block reduction of 13 values (6 T + 6 H + vcount) ----
    float vals[13];
    float vcf = 0.0f;
#pragma unroll
    for (int k = 0; k < NCLS; k++) {
        vals[k] = accT[k];
        float c = (float)((hcnt >> (9 * k)) & 511ull);
        vals[k + NCLS] = c;
        vcf += c;
    }
    vals[12] = vcf;

    __shared__ float sh[8][13];
    int lane = threadIdx.x & 31;
    int wid  = threadIdx.x >> 5;
#pragma unroll
    for (int k = 0; k < 13; k++) {
        float v = vals[k];
        v += __shfl_down_sync(0xffffffffu, v, 16);
        v += __shfl_down_sync(0xffffffffu, v, 8);
        v += __shfl_down_sync(0xffffffffu, v, 4);
        v += __shfl_down_sync(0xffffffffu, v, 2);
        v += __shfl_down_sync(0xffffffffu, v, 1);
        if (lane == 0) sh[wid][k] = v;
    }
    __syncthreads();
    if (wid == 0) {
#pragma unroll
        for (int k = 0; k < 13; k++) {
            float v = (lane < 8) ? sh[lane][k] : 0.0f;
            v += __shfl_down_sync(0xffffffffu, v, 4);
            v += __shfl_down_sync(0xffffffffu, v, 2);
            v += __shfl_down_sync(0xffffffffu, v, 1);
            if (lane == 0) atomicAdd(&g_part[n * 16 + k], v);
        }
    }

    // ---- last-block finalize ----
    __shared__ int is_last;
    __threadfence();
    if (threadIdx.x == 0) {
        unsigned int v = atomicAdd(&g_done, 1u);
        is_last = (v == (unsigned)(GX * NN) - 1u) ? 1 : 0;
    }
    __syncthreads();
    if (!is_last) return;

    __threadfence();
    if (wid == 0) {
        float num = 0.0f, den = 0.0f;
        if (lane < NN) {
            float T[NCLS], H[NCLS];
#pragma unroll
            for (int k = 0; k < NCLS; k++) {
                T[k] = __ldcg(&g_part[lane * 16 + k]);
                H[k] = __ldcg(&g_part[lane * 16 + NCLS + k]);
            }
            float vcn = __ldcg(&g_part[lane * 16 + 12]);
            float hs[NCLS], S = 0.0f;
#pragma unroll
            for (int k = 0; k < NCLS; k++) {
                hs[k] = (H[k] == 0.0f) ? 1.0f : H[k];   // empty classes -> 1 (RATIO=1)
                S += hs[k];
            }
            float c = 0.0f;
#pragma unroll
            for (int k = 0; k < NCLS; k++) c += (S / hs[k]) * T[k];  // weight = S/h
            num = c;
            den = vcn;
        }
        num += __shfl_down_sync(0xffffffffu, num, 4);
        den += __shfl_down_sync(0xffffffffu, den, 4);
        num += __shfl_down_sync(0xffffffffu, num, 2);
        den += __shfl_down_sync(0xffffffffu, den, 2);
        num += __shfl_down_sync(0xffffffffu, num, 1);
        den += __shfl_down_sync(0xffffffffu, den, 1);
        if (lane == 0) out[0] = -num / den;
    }
    __syncthreads();
    if (threadIdx.x < NN * 16) g_part[threadIdx.x] = 0.0f;
    if (threadIdx.x == 0)      g_done = 0;
}

extern "C" void kernel_launch(void* const* d_in, const int* in_sizes, int n_in,
                              void* d_out, int out_size) {
    const float* in;
    const int*   tg;
    if (in_sizes[0] > in_sizes[1]) {
        in = (const float*)d_in[0];
        tg = (const int*)d_in[1];
    } else {
        in = (const float*)d_in[1];
        tg = (const int*)d_in[0];
    }
    dim3 grid(GX, NN);
    fused_k<<<grid, TPB>>>(in, tg, (float*)d_out);
}

// round 8
// speedup vs baseline: 1.0562x; 1.0485x over previous
#include <cuda_runtime.h>
#include <cstdint>

#define NN      8
#define CC      21
#define HWP     262144           // 512*512
#define OLDCL   16
#define IGN     255
#define NCLS    6
#define GX      37               // blocks per sample; 37*8 = 296 = 2 per SM
#define TPB     256
#define CHUNK   512              // pixels per chunk
#define CPS     (HWP / CHUNK)    // 512 chunks per sample
#define CH_B    (CHUNK * 4)      // 2048 bytes per channel per chunk
#define STAGE_B ((CC + 1) * CH_B)        // 45056: 21 channels + targets
#define NSTG    2
#define SMEM_TOTAL (NSTG * STAGE_B + 16) // + 2 mbarriers

__device__ float        g_part[NN * 16];
__device__ unsigned int g_done = 0;

__device__ __forceinline__ uint32_t smem_u32(const void* p) {
    uint32_t a;
    asm("{ .reg .u64 t; cvta.to.shared.u64 t, %1; cvt.u32.u64 %0, t; }" : "=r"(a) : "l"(p));
    return a;
}
__device__ __forceinline__ void mbar_init(uint32_t mb, uint32_t cnt) {
    asm volatile("mbarrier.init.shared.b64 [%0], %1;" :: "r"(mb), "r"(cnt) : "memory");
}
__device__ __forceinline__ void mbar_expect(uint32_t mb, uint32_t bytes) {
    asm volatile("mbarrier.arrive.expect_tx.shared.b64 _, [%0], %1;"
                 :: "r"(mb), "r"(bytes) : "memory");
}
__device__ __forceinline__ void bulk_g2s(uint32_t dst, const void* src, uint32_t bytes,
                                         uint32_t mb) {
    asm volatile("cp.async.bulk.shared::cluster.global.mbarrier::complete_tx::bytes "
                 "[%0], [%1], %2, [%3];"
                 :: "r"(dst), "l"(src), "r"(bytes), "r"(mb) : "memory");
}
__device__ __forceinline__ void mbar_wait(uint32_t mb, uint32_t parity) {
    uint32_t done;
    asm volatile("{\n\t.reg .pred p;\n\t"
                 "mbarrier.try_wait.parity.acquire.cta.shared::cta.b64 p, [%1], %2;\n\t"
                 "selp.b32 %0, 1, 0, p;\n\t}"
                 : "=r"(done) : "r"(mb), "r"(parity) : "memory");
    if (!done) {
        asm volatile("{\n\t.reg .pred P1;\n\t"
                     "W%=:\n\t"
                     "mbarrier.try_wait.parity.acquire.cta.shared::cta.b64 P1, [%0], %1, 0x989680;\n\t"
                     "@P1 bra.uni D%=;\n\t"
                     "bra.uni W%=;\n\t"
                     "D%=:\n\t}"
                     :: "r"(mb), "r"(parity) : "memory");
    }
}
__device__ __forceinline__ float lg2f(float x) {
    float y; asm("lg2.approx.f32 %0,%1;" : "=f"(y) : "f"(x)); return y;
}

__global__ __launch_bounds__(TPB) void fused_k(const float* __restrict__ in,
                                               const int* __restrict__ tg,
                                               float* __restrict__ out) {
    extern __shared__ char sm[];
    const float LN2 = 0.6931471805599453f;
    int tid = threadIdx.x;
    int bx  = blockIdx.x;
    int n   = blockIdx.y;
    const float* base = in + (size_t)n * CC * HWP;
    const int*   t    = tg + (size_t)n * HWP;

    uint32_t smb  = smem_u32(sm);
    uint32_t mbar = smb + NSTG * STAGE_B;          // full[0], full[1]

    if (tid == 0) {
        mbar_init(mbar + 0, 1);
        mbar_init(mbar + 8, 1);
    }
    __syncthreads();

    int nch = (CPS - bx + GX - 1) / GX;            // 13 or 14 chunks for this block

    // prologue: fill both stages
    if (tid == 0) {
        for (int k = 0; k < NSTG && k < nch; k++) {
            int cid = bx + k * GX;
            uint32_t mb = mbar + 8 * k;
            uint32_t db = smb + k * STAGE_B;
            mbar_expect(mb, STAGE_B);
#pragma unroll
            for (int c = 0; c < CC; c++)
                bulk_g2s(db + c * CH_B, base + (size_t)c * HWP + cid * CHUNK, CH_B, mb);
            bulk_g2s(db + CC * CH_B, t + cid * CHUNK, CH_B, mb);
        }
    }

    float accT[NCLS] = {0, 0, 0, 0, 0, 0};
    unsigned long long hcnt = 0ull;                // 7 x 9-bit counters (6 = invalid)
    int fph[2] = {0, 0};

    for (int i = 0; i < nch; i++) {
        int s = i & 1;
        mbar_wait(mbar + 8 * s, fph[s]);
        fph[s] ^= 1;

        const char* db = sm + s * STAGE_B;
        // thread handles pixels 2*tid, 2*tid+1 of this chunk
        int2 tv = *reinterpret_cast<const int2*>(db + CC * CH_B + tid * 8);

        float2 ssum = make_float2(0.f, 0.f), s16v;
#pragma unroll
        for (int c = 0; c < OLDCL; c++) {
            float2 v = *reinterpret_cast<const float2*>(db + c * CH_B + tid * 8);
            ssum.x += __expf(v.x);
            ssum.y += __expf(v.y);
        }
        s16v = ssum;
#pragma unroll
        for (int c = OLDCL; c < CC; c++) {
            float2 v = *reinterpret_cast<const float2*>(db + c * CH_B + tid * 8);
            ssum.x += __expf(v.x);
            ssum.y += __expf(v.y);
        }

        int   tj[2] = {tv.x, tv.y};
        float sv[2] = {ssum.x, ssum.y};
        float qv[2] = {s16v.x, s16v.y};
#pragma unroll
        for (int px = 0; px < 2; px++) {
            int idx  = (tj[px] < OLDCL) ? 0 : (tj[px] - (OLDCL - 1));  // 0..5, big if IGN
            int code = (idx > 6) ? 6 : idx;
            hcnt += 1ull << (9 * code);
            float se = 0.0f;
            if (idx >= 1 && idx <= 5)               // label in 16..20: read from smem
                se = *reinterpret_cast<const float*>(db + tj[px] * CH_B + (2 * tid + px) * 4);
            float a  = lg2f(sv[px]);
            float lp = (idx == 0) ? ((lg2f(qv[px]) - a) * LN2)
                                  : fmaf(-LN2, a, se);
#pragma unroll
            for (int k = 0; k < NCLS; k++)
                if (idx == k) accT[k] += lp;
        }

        __syncthreads();                            // everyone done reading stage s
        if (tid == 0 && i + NSTG < nch) {           // refill stage s with chunk i+2
            int cid = bx + (i + NSTG) * GX;
            uint32_t mb = mbar + 8 * s;
            uint32_t dbs = smb + s * STAGE_B;
            mbar_expect(mb, STAGE_B);
#pragma unroll
            for (int c = 0; c < CC; c++)
                bulk_g2s(dbs + c * CH_B, base + (size_t)c * HWP + cid * CHUNK, CH_B, mb);
            bulk_g2s(dbs + CC * CH_B, t + cid * CHUNK, CH_B, mb);
        }
    }

    // ---- block reduction of 13 values (6 T + 6 H + vcount) ----
    float vals[13];
    float vcf = 0.0f;
#pragma unroll
    for (int k = 0; k < NCLS; k++) {
        vals[k] = accT[k];
        float c = (float)((hcnt >> (9 * k)) & 511ull);
        vals[k + NCLS] = c;
        vcf += c;
    }
    vals[12] = vcf;

    __shared__ float sh[8][13];
    int lane = tid & 31;
    int wid  = tid >> 5;
#pragma unroll
    for (int k = 0; k < 13; k++) {
        float v = vals[k];
        v += __shfl_down_sync(0xffffffffu, v, 16);
        v += __shfl_down_sync(0xffffffffu, v, 8);
        v += __shfl_down_sync(0xffffffffu, v, 4);
        v += __shfl_down_sync(0xffffffffu, v, 2);
        v += __shfl_down_sync(0xffffffffu, v, 1);
        if (lane == 0) sh[wid][k] = v;
    }
    __syncthreads();
    if (wid == 0) {
#pragma unroll
        for (int k = 0; k < 13; k++) {
            float v = (lane < 8) ? sh[lane][k] : 0.0f;
            v += __shfl_down_sync(0xffffffffu, v, 4);
            v += __shfl_down_sync(0xffffffffu, v, 2);
            v += __shfl_down_sync(0xffffffffu, v, 1);
            if (lane == 0) atomicAdd(&g_part[n * 16 + k], v);
        }
    }

    // ---- last-block finalize ----
    __shared__ int is_last;
    __threadfence();
    if (tid == 0) {
        unsigned int v = atomicAdd(&g_done, 1u);
        is_last = (v == (unsigned)(GX * NN) - 1u) ? 1 : 0;
    }
    __syncthreads();
    if (!is_last) return;

    __threadfence();
    if (wid == 0) {
        float num = 0.0f, den = 0.0f;
        if (lane < NN) {
            float T[NCLS], H[NCLS];
#pragma unroll
            for (int k = 0; k < NCLS; k++) {
                T[k] = __ldcg(&g_part[lane * 16 + k]);
                H[k] = __ldcg(&g_part[lane * 16 + NCLS + k]);
            }
            float vcn = __ldcg(&g_part[lane * 16 + 12]);
            float hs[NCLS], S = 0.0f;
#pragma unroll
            for (int k = 0; k < NCLS; k++) {
                hs[k] = (H[k] == 0.0f) ? 1.0f : H[k];   // empty classes -> 1 (RATIO=1)
                S += hs[k];
            }
            float c = 0.0f;
#pragma unroll
            for (int k = 0; k < NCLS; k++) c += (S / hs[k]) * T[k];   // weight = S/h
            num = c;
            den = vcn;
        }
        num += __shfl_down_sync(0xffffffffu, num, 4);
        den += __shfl_down_sync(0xffffffffu, den, 4);
        num += __shfl_down_sync(0xffffffffu, num, 2);
        den += __shfl_down_sync(0xffffffffu, den, 2);
        num += __shfl_down_sync(0xffffffffu, num, 1);
        den += __shfl_down_sync(0xffffffffu, den, 1);
        if (lane == 0) out[0] = -num / den;
    }
    __syncthreads();
    if (tid < NN * 16) g_part[tid] = 0.0f;
    if (tid == 0)      g_done = 0;
}

extern "C" void kernel_launch(void* const* d_in, const int* in_sizes, int n_in,
                              void* d_out, int out_size) {
    const float* in;
    const int*   tg;
    if (in_sizes[0] > in_sizes[1]) {
        in = (const float*)d_in[0];
        tg = (const int*)d_in[1];
    } else {
        in = (const float*)d_in[1];
        tg = (const int*)d_in[0];
    }
    static int configured = 0;
    if (!configured) {
        cudaFuncSetAttribute(fused_k, cudaFuncAttributeMaxDynamicSharedMemorySize,
                             SMEM_TOTAL);
        configured = 1;
    }
    dim3 grid(GX, NN);
    fused_k<<<grid, TPB, SMEM_TOTAL>>>(in, tg, (float*)d_out);
}